// round 4
// baseline (speedup 1.0000x reference)
#include <cuda_runtime.h>
#include <cstdint>

// Problem constants (fixed by the reference).
#define N_NODES 100000
#define N_EDGES 1600000
#define NF 32

// Scratch (device globals — no allocation allowed in kernel_launch).
__device__ float g_deg[N_NODES];
__device__ float g_dinv[N_NODES];

// Phase 0: init degree with the self-loop contribution.
__global__ void k_init_deg() {
    int i = blockIdx.x * blockDim.x + threadIdx.x;
    if (i < N_NODES) g_deg[i] = 1.0f;
}

// Phase 1: in-degree over dst (edge_index row 1). edge_index is int32
// (JAX x64 disabled downcasts the requested int64; R1 falsified the
// int64 layout empirically).
__global__ void k_count_deg(const int* __restrict__ ei) {
    int e = blockIdx.x * blockDim.x + threadIdx.x;
    if (e < N_EDGES) {
        int dst = __ldg(&ei[N_EDGES + e]);
        atomicAdd(&g_deg[dst], 1.0f);
    }
}

// Phase 2: dinv = deg^-0.5, and seed out with the self-loop term x[i]/deg[i].
__global__ void k_dinv_self(const float* __restrict__ x, float* __restrict__ out) {
    int i = blockIdx.x * blockDim.x + threadIdx.x;
    if (i < N_NODES) {
        float d = g_deg[i];           // >= 1 always (self loop)
        float di = rsqrtf(d);
        g_dinv[i] = di;
        float w = di * di;            // = 1/deg
        const float4* xi = (const float4*)(x + (size_t)i * NF);
        float4* oi = (float4*)(out + (size_t)i * NF);
        #pragma unroll
        for (int k = 0; k < NF / 4; k++) {
            float4 v = xi[k];
            v.x *= w; v.y *= w; v.z *= w; v.w *= w;
            oi[k] = v;
        }
    }
}

// Phase 3: edge scatter. 8 threads per edge; each lane handles one float4
// (16 B) of the 128 B feature row. Lanes of one edge read a contiguous
// 128 B line of x[src] and issue one vectorized red.global.add.v4.f32.
__global__ void __launch_bounds__(256)
k_scatter(const float* __restrict__ x,
          const int* __restrict__ ei,
          float* __restrict__ out) {
    long long tid = (long long)blockIdx.x * blockDim.x + threadIdx.x;
    int e  = (int)(tid >> 3);
    int f4 = (int)(tid & 7);
    if (e >= N_EDGES) return;

    int src = __ldg(&ei[e]);
    int dst = __ldg(&ei[N_EDGES + e]);
    float w = __ldg(&g_dinv[src]) * __ldg(&g_dinv[dst]);

    const float4* xs = (const float4*)(x + (size_t)src * NF);
    float4 v = __ldg(&xs[f4]);
    float a = v.x * w, b = v.y * w, c = v.z * w, d = v.w * w;

    float* op = out + (size_t)dst * NF + (size_t)f4 * 4;
    asm volatile("red.global.add.v4.f32 [%0], {%1, %2, %3, %4};"
                 :: "l"(op), "f"(a), "f"(b), "f"(c), "f"(d) : "memory");
}

extern "C" void kernel_launch(void* const* d_in, const int* in_sizes, int n_in,
                              void* d_out, int out_size) {
    const float* x  = (const float*)d_in[0];   // [N_NODES, 32] f32
    const int*   ei = (const int*)d_in[1];     // [2, N_EDGES] int32
    float* out = (float*)d_out;                // [N_NODES, 32] f32

    const int T = 256;
    k_init_deg<<<(N_NODES + T - 1) / T, T>>>();
    k_count_deg<<<(N_EDGES + T - 1) / T, T>>>(ei);
    k_dinv_self<<<(N_NODES + T - 1) / T, T>>>(x, out);

    long long work = (long long)N_EDGES * 8;
    k_scatter<<<(unsigned)((work + T - 1) / T), T>>>(x, ei, out);
}